// round 1
// baseline (speedup 1.0000x reference)
#include <cuda_runtime.h>

#define NB_CLUSTERS 128
#define NPTS 1024
#define THREADS 256
#define RPT 4  // rows per thread -> 256*4 = 1024 rows per CTA

// Partial sums: [dir][cluster], clusters 0..126 only (last cluster excluded by ref).
__device__ float g_partial[2 * (NB_CLUSTERS - 1)];

// One CTA per (cluster c in [0,126], direction dir).
// dir 0: rows = input_points, cols = output_points  (l1: for each a_i, min_j d)
// dir 1: rows = output_points, cols = input_points  (l2: for each b_j, min_i d)
// d(i,j) = |a_i|^2 + |b_j|^2 - 2 a_i.b_j ; we track min_j(|b_j|^2 - 2 a.b_j)
// and add |a_i|^2 once at the end.
__global__ void __launch_bounds__(THREADS, 2)
chamfer_rows_kernel(const float* __restrict__ in_pts,
                    const float* __restrict__ out_pts) {
    const int c   = blockIdx.x;   // 0..126
    const int dir = blockIdx.y;   // 0 or 1

    const float* rowp = (dir == 0 ? in_pts  : out_pts) + (size_t)c * NPTS * 3;
    const float* colp = (dir == 0 ? out_pts : in_pts ) + (size_t)c * NPTS * 3;

    __shared__ float4 sb[NPTS];   // (x, y, z, x^2+y^2+z^2) per column point

    const int tid = threadIdx.x;

    // Stage column points + norms into shared.
    for (int j = tid; j < NPTS; j += THREADS) {
        float x = colp[3 * j + 0];
        float y = colp[3 * j + 1];
        float z = colp[3 * j + 2];
        sb[j] = make_float4(x, y, z, fmaf(x, x, fmaf(y, y, z * z)));
    }
    __syncthreads();

    // Per-thread rows (coalesced: row = tid + r*THREADS).
    float a2x[RPT], a2y[RPT], a2z[RPT], an[RPT], m[RPT];
#pragma unroll
    for (int r = 0; r < RPT; r++) {
        int row = tid + r * THREADS;
        float x = rowp[3 * row + 0];
        float y = rowp[3 * row + 1];
        float z = rowp[3 * row + 2];
        a2x[r] = -2.0f * x;
        a2y[r] = -2.0f * y;
        a2z[r] = -2.0f * z;
        an[r]  = fmaf(x, x, fmaf(y, y, z * z));
        m[r]   = 3.4e38f;
    }

    // Main loop: 3 FFMA + 1 FMNMX per (row, j). LDS.128 broadcast, amortized x4.
#pragma unroll 4
    for (int j = 0; j < NPTS; j++) {
        float4 b = sb[j];
#pragma unroll
        for (int r = 0; r < RPT; r++) {
            float t = fmaf(a2z[r], b.z, b.w);
            t = fmaf(a2y[r], b.y, t);
            t = fmaf(a2x[r], b.x, t);
            m[r] = fminf(m[r], t);
        }
    }

    float s = 0.0f;
#pragma unroll
    for (int r = 0; r < RPT; r++) s += m[r] + an[r];

    // Deterministic block reduction.
#pragma unroll
    for (int off = 16; off > 0; off >>= 1)
        s += __shfl_down_sync(0xffffffffu, s, off);

    __shared__ float warpsum[THREADS / 32];
    if ((tid & 31) == 0) warpsum[tid >> 5] = s;
    __syncthreads();

    if (tid < THREADS / 32) {
        s = warpsum[tid];
#pragma unroll
        for (int off = (THREADS / 64); off > 0; off >>= 1)
            s += __shfl_down_sync(0xffu, s, off);
        if (tid == 0) g_partial[dir * (NB_CLUSTERS - 1) + c] = s;
    }
}

__global__ void reduce_partials_kernel(float* __restrict__ out) {
    const int n = 2 * (NB_CLUSTERS - 1);
    const int tid = threadIdx.x;
    float s = 0.0f;
    for (int i = tid; i < n; i += 256) s += g_partial[i];
#pragma unroll
    for (int off = 16; off > 0; off >>= 1)
        s += __shfl_down_sync(0xffffffffu, s, off);
    __shared__ float ws[8];
    if ((tid & 31) == 0) ws[tid >> 5] = s;
    __syncthreads();
    if (tid < 8) {
        s = ws[tid];
#pragma unroll
        for (int off = 4; off > 0; off >>= 1)
            s += __shfl_down_sync(0xffu, s, off);
        if (tid == 0) out[0] = s;
    }
}

extern "C" void kernel_launch(void* const* d_in, const int* in_sizes, int n_in,
                              void* d_out, int out_size) {
    // metadata order: input_points, input_clusters, output_points, output_clusters
    const float* in_pts  = (const float*)d_in[0];
    const float* out_pts = (const float*)d_in[2];
    float* out = (float*)d_out;

    dim3 grid(NB_CLUSTERS - 1, 2);
    chamfer_rows_kernel<<<grid, THREADS>>>(in_pts, out_pts);
    reduce_partials_kernel<<<1, 256>>>(out);
}

// round 2
// speedup vs baseline: 1.0728x; 1.0728x over previous
#include <cuda_runtime.h>

#define NB_CLUSTERS 128
#define NPTS 1024
#define NPAIRS (NPTS / 2)
#define THREADS 64
#define RPT 4               // rows per thread -> 64*4 = 256 rows per CTA
#define RBLKS 4             // row blocks per (cluster, dir)
#define NUNITS ((NB_CLUSTERS - 1) * 2 * RBLKS)   // 127*2*4 = 1016

typedef unsigned long long ull;

__device__ float g_partial[NUNITS];

// One CTA per (cluster c in [0,126], dir, rblk).
// dir 0: rows = input_points, cols = output_points
// dir 1: rows = output_points, cols = input_points
// d(i,j) = |a_i|^2 + |b_j|^2 - 2 a_i.b_j ; track min_j(|b_j|^2 - 2 a.b_j),
// add |a_i|^2 at the end. Columns processed 2-at-a-time via fma.rn.f32x2.
__global__ void __launch_bounds__(THREADS)
chamfer_rows_kernel(const float* __restrict__ in_pts,
                    const float* __restrict__ out_pts) {
    const int unit = blockIdx.x;
    const int c    = unit >> 3;          // 0..126
    const int dir  = (unit >> 2) & 1;    // 0 or 1
    const int rblk = unit & 3;           // 0..3

    const float* rowp = (dir == 0 ? in_pts  : out_pts) + (size_t)c * NPTS * 3;
    const float* colp = (dir == 0 ? out_pts : in_pts ) + (size_t)c * NPTS * 3;

    // Column pairs: sxy[jp] = {pack(x0,x1), pack(y0,y1)}, szw[jp] = {pack(z0,z1), pack(w0,w1)}
    __shared__ ulonglong2 sxy[NPAIRS];
    __shared__ ulonglong2 szw[NPAIRS];

    const int tid = threadIdx.x;

    // Stage column point pairs + norms into shared.
    for (int jp = tid; jp < NPAIRS; jp += THREADS) {
        const float* p = colp + 6 * jp;
        float x0 = p[0], y0 = p[1], z0 = p[2];
        float x1 = p[3], y1 = p[4], z1 = p[5];
        float w0 = fmaf(x0, x0, fmaf(y0, y0, z0 * z0));
        float w1 = fmaf(x1, x1, fmaf(y1, y1, z1 * z1));
        ulonglong2 vxy, vzw;
        asm("mov.b64 %0, {%1, %2};" : "=l"(vxy.x) : "f"(x0), "f"(x1));
        asm("mov.b64 %0, {%1, %2};" : "=l"(vxy.y) : "f"(y0), "f"(y1));
        asm("mov.b64 %0, {%1, %2};" : "=l"(vzw.x) : "f"(z0), "f"(z1));
        asm("mov.b64 %0, {%1, %2};" : "=l"(vzw.y) : "f"(w0), "f"(w1));
        sxy[jp] = vxy;
        szw[jp] = vzw;
    }
    __syncthreads();

    // Per-thread rows (row = rblk*256 + tid + r*THREADS).
    ull A2X[RPT], A2Y[RPT], A2Z[RPT];
    float an[RPT], m[RPT];
#pragma unroll
    for (int r = 0; r < RPT; r++) {
        int row = rblk * 256 + tid + r * THREADS;
        float x = rowp[3 * row + 0];
        float y = rowp[3 * row + 1];
        float z = rowp[3 * row + 2];
        float ax = -2.0f * x, ay = -2.0f * y, az = -2.0f * z;
        asm("mov.b64 %0, {%1, %1};" : "=l"(A2X[r]) : "f"(ax));
        asm("mov.b64 %0, {%1, %1};" : "=l"(A2Y[r]) : "f"(ay));
        asm("mov.b64 %0, {%1, %1};" : "=l"(A2Z[r]) : "f"(az));
        an[r] = fmaf(x, x, fmaf(y, y, z * z));
        m[r]  = 3.4e38f;
    }

    // Main loop: per column pair, per row: 3 FFMA2 + 2 FMNMX.
#pragma unroll 2
    for (int jp = 0; jp < NPAIRS; jp++) {
        ulonglong2 vxy = sxy[jp];
        ulonglong2 vzw = szw[jp];
#pragma unroll
        for (int r = 0; r < RPT; r++) {
            float lo, hi;
            asm("{\n\t"
                ".reg .b64 t;\n\t"
                "fma.rn.f32x2 t, %2, %3, %4;\n\t"
                "fma.rn.f32x2 t, %5, %6, t;\n\t"
                "fma.rn.f32x2 t, %7, %8, t;\n\t"
                "mov.b64 {%0, %1}, t;\n\t"
                "}"
                : "=f"(lo), "=f"(hi)
                : "l"(A2Z[r]), "l"(vzw.x), "l"(vzw.y),
                  "l"(A2Y[r]), "l"(vxy.y),
                  "l"(A2X[r]), "l"(vxy.x));
            m[r] = fminf(m[r], fminf(lo, hi));
        }
    }

    float s = 0.0f;
#pragma unroll
    for (int r = 0; r < RPT; r++) s += m[r] + an[r];

    // Deterministic block reduction (64 threads = 2 warps).
#pragma unroll
    for (int off = 16; off > 0; off >>= 1)
        s += __shfl_down_sync(0xffffffffu, s, off);

    __shared__ float warpsum[2];
    if ((tid & 31) == 0) warpsum[tid >> 5] = s;
    __syncthreads();
    if (tid == 0) g_partial[unit] = warpsum[0] + warpsum[1];
}

__global__ void reduce_partials_kernel(float* __restrict__ out) {
    const int tid = threadIdx.x;
    float s = 0.0f;
    for (int i = tid; i < NUNITS; i += 256) s += g_partial[i];
#pragma unroll
    for (int off = 16; off > 0; off >>= 1)
        s += __shfl_down_sync(0xffffffffu, s, off);
    __shared__ float ws[8];
    if ((tid & 31) == 0) ws[tid >> 5] = s;
    __syncthreads();
    if (tid < 8) {
        s = ws[tid];
#pragma unroll
        for (int off = 4; off > 0; off >>= 1)
            s += __shfl_down_sync(0xffu, s, off);
        if (tid == 0) out[0] = s;
    }
}

extern "C" void kernel_launch(void* const* d_in, const int* in_sizes, int n_in,
                              void* d_out, int out_size) {
    const float* in_pts  = (const float*)d_in[0];
    const float* out_pts = (const float*)d_in[2];
    float* out = (float*)d_out;

    chamfer_rows_kernel<<<NUNITS, THREADS>>>(in_pts, out_pts);
    reduce_partials_kernel<<<1, 256>>>(out);
}